// round 2
// baseline (speedup 1.0000x reference)
#include <cuda_runtime.h>
#include <cstdint>

#define N_NODES 100000
#define N_EDGES 6400000
#define TOKEN_DIM 16

// Scratch accumulator: colsum[n] = sum over edges e with row[e]==n of x[col[e]]
// (local_field[n] = x[n] * colsum[n], multiply deferred to the MLP kernel).
__device__ float g_acc[N_NODES];

// ---------------------------------------------------------------------------
// Kernel 0: zero the accumulator (graph replays require re-init every launch)
// ---------------------------------------------------------------------------
__global__ void zero_kernel() {
    int i = blockIdx.x * blockDim.x + threadIdx.x;
    if (i < N_NODES) g_acc[i] = 0.0f;
}

// ---------------------------------------------------------------------------
// Kernel 1: edge scatter. edge_index is INT32 (JAX canonicalizes int64->int32
// without x64 mode). 4 edges per thread via int4 16B loads. The 51.2MB index
// stream is the HBM bottleneck; x (400KB) is L2-resident so gathers are L2
// hits. atomicAdd with unused result compiles to REDG (no return trip).
// ---------------------------------------------------------------------------
__global__ void __launch_bounds__(256) edge_kernel(
    const int* __restrict__ ei, const float* __restrict__ x) {
    const int4* rows = reinterpret_cast<const int4*>(ei);
    const int4* cols = reinterpret_cast<const int4*>(ei + N_EDGES);
    int t = blockIdx.x * blockDim.x + threadIdx.x;   // thread handles edges [4t, 4t+4)

    int4 r = rows[t];
    int4 c = cols[t];

    float v0 = __ldg(&x[c.x]);
    float v1 = __ldg(&x[c.y]);
    float v2 = __ldg(&x[c.z]);
    float v3 = __ldg(&x[c.w]);

    atomicAdd(&g_acc[r.x], v0);
    atomicAdd(&g_acc[r.y], v1);
    atomicAdd(&g_acc[r.z], v2);
    atomicAdd(&g_acc[r.w], v3);
}

// ---------------------------------------------------------------------------
// Kernel 2: per-node 2->16->16 MLP with ReLU. Weights staged in shared
// (all-lanes-same-address LDS = broadcast, conflict-free). float4 stores.
// ---------------------------------------------------------------------------
__global__ void __launch_bounds__(256) mlp_kernel(
    const float* __restrict__ x,
    const float* __restrict__ w1, const float* __restrict__ b1,
    const float* __restrict__ w2, const float* __restrict__ b2,
    float* __restrict__ out) {
    __shared__ float s_w1[2 * TOKEN_DIM];            // w1[j][k], row-major [16,2]
    __shared__ float s_b1[TOKEN_DIM];
    __shared__ float s_w2[TOKEN_DIM * TOKEN_DIM];    // w2[j][k], row-major [16,16]
    __shared__ float s_b2[TOKEN_DIM];

    int tid = threadIdx.x;
    if (tid < 2 * TOKEN_DIM)         s_w1[tid] = w1[tid];
    if (tid < TOKEN_DIM)             s_b1[tid] = b1[tid];
    if (tid < TOKEN_DIM * TOKEN_DIM) s_w2[tid] = w2[tid];
    if (tid >= 32 && tid < 32 + TOKEN_DIM) s_b2[tid - 32] = b2[tid - 32];
    __syncthreads();

    int i = blockIdx.x * blockDim.x + tid;
    if (i >= N_NODES) return;

    float f0 = x[i];
    float f1 = f0 * g_acc[i];                        // local_field = x[n] * colsum[n]

    float h[TOKEN_DIM];
#pragma unroll
    for (int j = 0; j < TOKEN_DIM; j++) {
        float v = fmaf(f0, s_w1[2 * j], fmaf(f1, s_w1[2 * j + 1], s_b1[j]));
        h[j] = fmaxf(v, 0.0f);
    }

    float o[TOKEN_DIM];
#pragma unroll
    for (int j = 0; j < TOKEN_DIM; j++) {
        float v = s_b2[j];
#pragma unroll
        for (int k = 0; k < TOKEN_DIM; k++)
            v = fmaf(h[k], s_w2[j * TOKEN_DIM + k], v);
        o[j] = fmaxf(v, 0.0f);
    }

    float4* outv = reinterpret_cast<float4*>(out + (size_t)i * TOKEN_DIM);
#pragma unroll
    for (int j = 0; j < 4; j++)
        outv[j] = make_float4(o[4 * j], o[4 * j + 1], o[4 * j + 2], o[4 * j + 3]);
}

// ---------------------------------------------------------------------------
// kernel_launch: inputs per metadata order:
//   d_in[0] = x          float32  [100000, 1]
//   d_in[1] = edge_index int32    [2, 6400000]  (JAX canonicalized from int64)
//   d_in[2] = w1         float32  [16, 2]
//   d_in[3] = b1         float32  [16]
//   d_in[4] = w2         float32  [16, 16]
//   d_in[5] = b2         float32  [16]
//   d_out   = tokens     float32  [100000, 16]
// ---------------------------------------------------------------------------
extern "C" void kernel_launch(void* const* d_in, const int* in_sizes, int n_in,
                              void* d_out, int out_size) {
    const float* x  = (const float*)d_in[0];
    const int*   ei = (const int*)d_in[1];
    const float* w1 = (const float*)d_in[2];
    const float* b1 = (const float*)d_in[3];
    const float* w2 = (const float*)d_in[4];
    const float* b2 = (const float*)d_in[5];
    float* out = (float*)d_out;

    zero_kernel<<<(N_NODES + 255) / 256, 256>>>();

    // 6.4M edges, 4 per thread -> 1.6M threads -> exactly 6250 blocks of 256
    edge_kernel<<<N_EDGES / 4 / 256, 256>>>(ei, x);

    mlp_kernel<<<(N_NODES + 255) / 256, 256>>>(x, w1, b1, w2, b2, out);
}